// round 16
// baseline (speedup 1.0000x reference)
#include <cuda_runtime.h>
#include <cuda_bf16.h>
#include <cstdint>

// LBP layer, fully fused, ZERO-SMEM warp-strip design, depth-1 prefetch,
// scalar FFMA-immediate LBP epilogue (no packed weight registers).
// Each lane loads its own 2 RGB pixels per row straight from GMEM (coalesced
// float2 x3), computes gray, gets +2/+3 columns via shfl_down, rolling
// compare + LBP core. No shared memory, no __syncthreads.
//   gray = dot(rgb, [0.2989, 0.587, 0.114])                (zero-padded outside)
//   s(y,x) = #{3x3 nbrs (incl. center): gray >= gray(y,x)} (s = 0 outside image)
//   lbp(y,x) = 1*s(y-1,x-1)+2*s(y-1,x)+4*s(y-1,x+1)
//            +128*s(y,x-1)           +8*s(y,x+1)
//            +64*s(y+1,x-1)+32*s(y+1,x)+16*s(y+1,x+1)
// Fixed shapes: N=32, H=W=512, C=3. Output [N,H,W,1] fp32.

#define OUT_PW   60          // output cols per x-tile (x0 % 4 == 0)
#define RPW      16          // output rows per warp strip
#define WARPS_PB 2           // warps per block (stacked vertically)
#define NTHREADS 64
#define GX 9
#define GYB 16               // blocks in y: each covers WARPS_PB*RPW = 32 rows

struct Raw { float2 p0, p1, p2; };

__device__ __forceinline__ Raw ldraw(const float* __restrict__ p, bool ok) {
    Raw r;
    if (ok) {
        r.p0 = __ldg((const float2*)p);
        r.p1 = __ldg((const float2*)(p + 2));
        r.p2 = __ldg((const float2*)(p + 4));
    } else {
        r.p0 = make_float2(0.f, 0.f);
        r.p1 = make_float2(0.f, 0.f);
        r.p2 = make_float2(0.f, 0.f);
    }
    return r;
}

__device__ __forceinline__ void gray2(const Raw& r, float& g0, float& g1) {
    g0 = fmaf(0.2989f, r.p0.x, fmaf(0.587f, r.p0.y, 0.114f * r.p1.x));
    g1 = fmaf(0.2989f, r.p1.y, fmaf(0.587f, r.p2.x, 0.114f * r.p2.y));
}

// One warp strip: RPW output rows x 62 s-cols (60 stored), rolling registers.
template<bool XE, bool YE>
__device__ __forceinline__ void lbp_strip(
    const float* __restrict__ base,   // image n, RGB
    float* __restrict__ outn,         // image n, out
    int x0, int r0, int lane, int H, int W)
{
    const int c0  = x0 - 2 + 2 * lane;        // lane's gray cols c0, c0+1 (even)
    const int csA = c0 + 1;                   // lane's s cols csA, csA+1
    const bool colA = XE ? ((unsigned)csA       < (unsigned)W) : true;
    const bool colB = XE ? ((unsigned)(csA + 1) < (unsigned)W) : true;
    const bool ldOk = XE ? ((c0 >= 0) && (c0 < W)) : true;   // both-or-neither (even)

    const int rstep = W * 3;                  // fits easily in int
    const float* rpA = base + ((long long)(r0 - 2) * W + c0) * 3;

    // preamble: rows r0-2, r0-1; prefetch row r0 (always < H)
    const bool okA = ldOk && (!YE || (unsigned)(r0 - 2) < (unsigned)H);
    Raw ra = ldraw(rpA, okA);
    const bool okB = ldOk && (!YE || (unsigned)(r0 - 1) < (unsigned)H);
    Raw rb = ldraw(rpA + rstep, okB);
    Raw rq = ldraw(rpA + 2 * rstep, ldOk);    // row r0
    const float* rpn = rpA + 3 * rstep;       // next prefetch: row r0+1

    float a0, a1; gray2(ra, a0, a1);
    float a2 = __shfl_down_sync(0xffffffffu, a0, 1);   // col c0+2
    float a3 = __shfl_down_sync(0xffffffffu, a1, 1);   // col c0+3
    float b0, b1; gray2(rb, b0, b1);
    float b2 = __shfl_down_sync(0xffffffffu, b0, 1);
    float b3 = __shfl_down_sync(0xffffffffu, b1, 1);

    // rolling s state: s2_* = two rows ago, s1_* = one row ago (cols csA-? rel)
    float s2_0 = 0.f, s2_1 = 0.f, s2_2 = 0.f, s2_3 = 0.f;
    float s1_0 = 0.f, s1_1 = 0.f, s1_2 = 0.f, s1_3 = 0.f;

    const bool doStore = (lane <= 29);        // lanes 0..29 -> cols x0 .. x0+59
    float* op = outn + (size_t)r0 * W + (x0 + 2 * lane);

    #pragma unroll
    for (int i = 0; i < RPW + 2; i++) {
        const Raw cur = rq;
        if (i < RPW + 1) {                    // prefetch row r0+i+1
            const bool okn = ldOk && (!YE || (r0 + i + 1) < H);
            rq = ldraw(rpn, okn);
            rpn += rstep;
        }
        float t0, t1; gray2(cur, t0, t1);
        const float t2 = __shfl_down_sync(0xffffffffu, t0, 1);
        const float t3 = __shfl_down_sync(0xffffffffu, t1, 1);

        // two independent compare-accumulate chains (centers b1, b2)
        float cA = 1.0f, cB = 1.0f;
        cA += (a0 >= b1) ? 1.0f : 0.0f;
        cB += (a1 >= b2) ? 1.0f : 0.0f;
        cA += (a1 >= b1) ? 1.0f : 0.0f;
        cB += (a2 >= b2) ? 1.0f : 0.0f;
        cA += (a2 >= b1) ? 1.0f : 0.0f;
        cB += (a3 >= b2) ? 1.0f : 0.0f;
        cA += (b0 >= b1) ? 1.0f : 0.0f;
        cB += (b1 >= b2) ? 1.0f : 0.0f;
        cA += (b2 >= b1) ? 1.0f : 0.0f;
        cB += (b3 >= b2) ? 1.0f : 0.0f;
        cA += (t0 >= b1) ? 1.0f : 0.0f;
        cB += (t1 >= b2) ? 1.0f : 0.0f;
        cA += (t1 >= b1) ? 1.0f : 0.0f;
        cB += (t2 >= b2) ? 1.0f : 0.0f;
        cA += (t2 >= b1) ? 1.0f : 0.0f;
        cB += (t3 >= b2) ? 1.0f : 0.0f;

        float sa, sb;
        if (YE) {
            const int ys = r0 - 1 + i;
            const bool rowOk = (unsigned)ys < (unsigned)H;
            sa = (rowOk && colA) ? cA : 0.0f;     // zero-pad s
            sb = (rowOk && colB) ? cB : 0.0f;
        } else if (XE) {
            sa = colA ? cA : 0.0f;
            sb = colB ? cB : 0.0f;
        } else {
            sa = cA;
            sb = cB;
        }

        const float na = __shfl_down_sync(0xffffffffu, sa, 1);  // s col csA+2
        const float nb = __shfl_down_sync(0xffffffffu, sb, 1);  // s col csA+3

        if (i >= 2) {
            // emit row ys-1, cols x0+2*lane, x0+2*lane+1  (FFMA-imm chain)
            float v0 = s2_0;
            v0 = fmaf(  2.0f, s2_1, v0);
            v0 = fmaf(  4.0f, s2_2, v0);
            v0 = fmaf(128.0f, s1_0, v0);
            v0 = fmaf(  8.0f, s1_2, v0);
            v0 = fmaf( 64.0f, sa,   v0);
            v0 = fmaf( 32.0f, sb,   v0);
            v0 = fmaf( 16.0f, na,   v0);

            float v1 = s2_1;
            v1 = fmaf(  2.0f, s2_2, v1);
            v1 = fmaf(  4.0f, s2_3, v1);
            v1 = fmaf(128.0f, s1_1, v1);
            v1 = fmaf(  8.0f, s1_3, v1);
            v1 = fmaf( 64.0f, sb,   v1);
            v1 = fmaf( 32.0f, na,   v1);
            v1 = fmaf( 16.0f, nb,   v1);

            if (doStore) *(float2*)op = make_float2(v0, v1);
            op += W;
        }

        s2_0 = s1_0; s2_1 = s1_1; s2_2 = s1_2; s2_3 = s1_3;
        s1_0 = sa;   s1_1 = sb;   s1_2 = na;   s1_3 = nb;
        a0 = b0; a1 = b1; a2 = b2; a3 = b3;
        b0 = t0; b1 = t1; b2 = t2; b3 = t3;
    }
}

__global__ __launch_bounds__(NTHREADS, 14) void lbp_nosmem_kernel(
    const float* __restrict__ in,   // [N, H, W, 3]
    float* __restrict__ out,        // [N, H, W, 1]
    int H, int W)
{
    const int lane = threadIdx.x & 31;
    const int wrp  = threadIdx.x >> 5;
    const int bx = blockIdx.x, byb = blockIdx.y, n = blockIdx.z;

    const bool xe = (bx == 0) || (bx == GX - 1);
    const bool ye = (byb == 0) || (byb == GYB - 1);

    int x0 = bx * OUT_PW;
    if (x0 + OUT_PW > W) x0 = W - OUT_PW;     // 452 for last block (%4==0)
    const int r0 = (byb * WARPS_PB + wrp) * RPW;

    const float* base = in + (size_t)n * H * W * 3;
    float* outn = out + (size_t)n * H * W;

    if (!xe && !ye)      lbp_strip<false, false>(base, outn, x0, r0, lane, H, W);
    else if (!xe)        lbp_strip<false, true >(base, outn, x0, r0, lane, H, W);
    else if (!ye)        lbp_strip<true,  false>(base, outn, x0, r0, lane, H, W);
    else                 lbp_strip<true,  true >(base, outn, x0, r0, lane, H, W);
}

extern "C" void kernel_launch(void* const* d_in, const int* in_sizes, int n_in,
                              void* d_out, int out_size)
{
    const float* in = (const float*)d_in[0];
    float* out = (float*)d_out;

    const int H = 512, W = 512;
    const int N = in_sizes[0] / (H * W * 3);

    dim3 grid(GX, GYB, N);   // 9 x 16 x 32 = 4608 blocks of 64 threads
    lbp_nosmem_kernel<<<grid, NTHREADS>>>(in, out, H, W);
}

// round 17
// speedup vs baseline: 1.0607x; 1.0607x over previous
#include <cuda_runtime.h>
#include <cuda_bf16.h>
#include <cstdint>

// LBP layer, fully fused, ZERO-SMEM warp-strip design, depth-1 prefetch,
// running-accumulator LBP epilogue (4 accumulator regs instead of 8 s-regs).
// Each lane loads its own 2 RGB pixels per row straight from GMEM (coalesced
// float2 x3), computes gray, gets +2/+3 columns via shfl_down.
// No shared memory, no __syncthreads.
//   gray = dot(rgb, [0.2989, 0.587, 0.114])                (zero-padded outside)
//   s(y,x) = #{3x3 nbrs (incl. center): gray >= gray(y,x)} (s = 0 outside image)
//   lbp(y,x) = 1*s(y-1,x-1)+2*s(y-1,x)+4*s(y-1,x+1)
//            +128*s(y,x-1)           +8*s(y,x+1)
//            +64*s(y+1,x-1)+32*s(y+1,x)+16*s(y+1,x+1)
// Fixed shapes: N=32, H=W=512, C=3. Output [N,H,W,1] fp32.

#define OUT_PW   60          // output cols per x-tile (x0 % 4 == 0)
#define RPW      16          // output rows per warp strip
#define WARPS_PB 2           // warps per block (stacked vertically)
#define NTHREADS 64
#define GX 9
#define GYB 16               // blocks in y: each covers WARPS_PB*RPW = 32 rows

struct Raw { float2 p0, p1, p2; };

__device__ __forceinline__ Raw ldraw(const float* __restrict__ p, bool ok) {
    Raw r;
    if (ok) {
        r.p0 = __ldg((const float2*)p);
        r.p1 = __ldg((const float2*)(p + 2));
        r.p2 = __ldg((const float2*)(p + 4));
    } else {
        r.p0 = make_float2(0.f, 0.f);
        r.p1 = make_float2(0.f, 0.f);
        r.p2 = make_float2(0.f, 0.f);
    }
    return r;
}

__device__ __forceinline__ void gray2(const Raw& r, float& g0, float& g1) {
    g0 = fmaf(0.2989f, r.p0.x, fmaf(0.587f, r.p0.y, 0.114f * r.p1.x));
    g1 = fmaf(0.2989f, r.p1.y, fmaf(0.587f, r.p2.x, 0.114f * r.p2.y));
}

// One warp strip: RPW output rows x 62 s-cols (60 stored), rolling registers.
template<bool XE, bool YE>
__device__ __forceinline__ void lbp_strip(
    const float* __restrict__ base,   // image n, RGB
    float* __restrict__ outn,         // image n, out
    int x0, int r0, int lane, int H, int W)
{
    const int c0  = x0 - 2 + 2 * lane;        // lane's gray cols c0, c0+1 (even)
    const int csA = c0 + 1;                   // lane's s cols csA, csA+1
    const bool colA = XE ? ((unsigned)csA       < (unsigned)W) : true;
    const bool colB = XE ? ((unsigned)(csA + 1) < (unsigned)W) : true;
    const bool ldOk = XE ? ((c0 >= 0) && (c0 < W)) : true;   // both-or-neither (even)

    const int rstep = W * 3;
    const float* rpA = base + ((long long)(r0 - 2) * W + c0) * 3;

    // preamble: rows r0-2, r0-1; prefetch row r0 (always < H)
    const bool okA = ldOk && (!YE || (unsigned)(r0 - 2) < (unsigned)H);
    Raw ra = ldraw(rpA, okA);
    const bool okB = ldOk && (!YE || (unsigned)(r0 - 1) < (unsigned)H);
    Raw rb = ldraw(rpA + rstep, okB);
    Raw rq = ldraw(rpA + 2 * rstep, ldOk);    // row r0
    const float* rpn = rpA + 3 * rstep;       // next prefetch: row r0+1

    float a0, a1; gray2(ra, a0, a1);
    float a2 = __shfl_down_sync(0xffffffffu, a0, 1);   // col c0+2
    float a3 = __shfl_down_sync(0xffffffffu, a1, 1);   // col c0+3
    float b0, b1; gray2(rb, b0, b1);
    float b2 = __shfl_down_sync(0xffffffffu, b0, 1);
    float b3 = __shfl_down_sync(0xffffffffu, b1, 1);

    // running accumulators for the two output columns:
    //   w = top-row terms (1,2,4) from the newest s row
    //   u = w_prev + mid-row terms (128, 8)
    float u0 = 0.f, u1 = 0.f, w0 = 0.f, w1 = 0.f;

    const bool doStore = (lane <= 29);        // lanes 0..29 -> cols x0 .. x0+59
    float* op = outn + (size_t)r0 * W + (x0 + 2 * lane);

    #pragma unroll
    for (int i = 0; i < RPW + 2; i++) {
        const Raw cur = rq;
        if (i < RPW + 1) {                    // prefetch row r0+i+1
            const bool okn = ldOk && (!YE || (r0 + i + 1) < H);
            rq = ldraw(rpn, okn);
            rpn += rstep;
        }
        float t0, t1; gray2(cur, t0, t1);
        const float t2 = __shfl_down_sync(0xffffffffu, t0, 1);
        const float t3 = __shfl_down_sync(0xffffffffu, t1, 1);

        // two independent compare-accumulate chains (centers b1, b2)
        float cA = 1.0f, cB = 1.0f;
        cA += (a0 >= b1) ? 1.0f : 0.0f;
        cB += (a1 >= b2) ? 1.0f : 0.0f;
        cA += (a1 >= b1) ? 1.0f : 0.0f;
        cB += (a2 >= b2) ? 1.0f : 0.0f;
        cA += (a2 >= b1) ? 1.0f : 0.0f;
        cB += (a3 >= b2) ? 1.0f : 0.0f;
        cA += (b0 >= b1) ? 1.0f : 0.0f;
        cB += (b1 >= b2) ? 1.0f : 0.0f;
        cA += (b2 >= b1) ? 1.0f : 0.0f;
        cB += (b3 >= b2) ? 1.0f : 0.0f;
        cA += (t0 >= b1) ? 1.0f : 0.0f;
        cB += (t1 >= b2) ? 1.0f : 0.0f;
        cA += (t1 >= b1) ? 1.0f : 0.0f;
        cB += (t2 >= b2) ? 1.0f : 0.0f;
        cA += (t2 >= b1) ? 1.0f : 0.0f;
        cB += (t3 >= b2) ? 1.0f : 0.0f;

        float sa, sb;
        if (YE) {
            const int ys = r0 - 1 + i;
            const bool rowOk = (unsigned)ys < (unsigned)H;
            sa = (rowOk && colA) ? cA : 0.0f;     // zero-pad s
            sb = (rowOk && colB) ? cB : 0.0f;
        } else if (XE) {
            sa = colA ? cA : 0.0f;
            sb = colB ? cB : 0.0f;
        } else {
            sa = cA;
            sb = cB;
        }

        const float na = __shfl_down_sync(0xffffffffu, sa, 1);  // s col csA+2
        const float nb = __shfl_down_sync(0xffffffffu, sb, 1);  // s col csA+3

        if (i >= 2) {
            // emit row ys-1: bottom-row terms (64, 32, 16) close the sum
            const float v0 = fmaf(64.0f, sa, fmaf(32.0f, sb, fmaf(16.0f, na, u0)));
            const float v1 = fmaf(64.0f, sb, fmaf(32.0f, na, fmaf(16.0f, nb, u1)));
            if (doStore) *(float2*)op = make_float2(v0, v1);
            op += W;
        }
        // roll accumulators: u <- w + (128, 8) of this s row; w <- (1, 2, 4)
        u0 = fmaf(128.0f, sa, fmaf(8.0f, na, w0));
        u1 = fmaf(128.0f, sb, fmaf(8.0f, nb, w1));
        w0 = fmaf(4.0f, na, fmaf(2.0f, sb, sa));
        w1 = fmaf(4.0f, nb, fmaf(2.0f, na, sb));

        a0 = b0; a1 = b1; a2 = b2; a3 = b3;
        b0 = t0; b1 = t1; b2 = t2; b3 = t3;
    }
}

__global__ __launch_bounds__(NTHREADS, 16) void lbp_nosmem_kernel(
    const float* __restrict__ in,   // [N, H, W, 3]
    float* __restrict__ out,        // [N, H, W, 1]
    int H, int W)
{
    const int lane = threadIdx.x & 31;
    const int wrp  = threadIdx.x >> 5;
    const int bx = blockIdx.x, byb = blockIdx.y, n = blockIdx.z;

    const bool xe = (bx == 0) || (bx == GX - 1);
    const bool ye = (byb == 0) || (byb == GYB - 1);

    int x0 = bx * OUT_PW;
    if (x0 + OUT_PW > W) x0 = W - OUT_PW;     // 452 for last block (%4==0)
    const int r0 = (byb * WARPS_PB + wrp) * RPW;

    const float* base = in + (size_t)n * H * W * 3;
    float* outn = out + (size_t)n * H * W;

    if (!xe && !ye)      lbp_strip<false, false>(base, outn, x0, r0, lane, H, W);
    else if (!xe)        lbp_strip<false, true >(base, outn, x0, r0, lane, H, W);
    else if (!ye)        lbp_strip<true,  false>(base, outn, x0, r0, lane, H, W);
    else                 lbp_strip<true,  true >(base, outn, x0, r0, lane, H, W);
}

extern "C" void kernel_launch(void* const* d_in, const int* in_sizes, int n_in,
                              void* d_out, int out_size)
{
    const float* in = (const float*)d_in[0];
    float* out = (float*)d_out;

    const int H = 512, W = 512;
    const int N = in_sizes[0] / (H * W * 3);

    dim3 grid(GX, GYB, N);   // 9 x 16 x 32 = 4608 blocks of 64 threads
    lbp_nosmem_kernel<<<grid, NTHREADS>>>(in, out, H, W);
}